// round 1
// baseline (speedup 1.0000x reference)
#include <cuda_runtime.h>
#include <math.h>

// Problem constants (from reference)
#define N_NODES  100000
#define N_EDGES  3200000
#define N_GRAPHS 64
#define F_IN     128
#define HID      256
#define N_CLS    2

// ---------------------------------------------------------------------------
// Scratch (static __device__ arrays — allocation-free per harness rules)
// ---------------------------------------------------------------------------
__device__ __align__(16) float g_dinv[N_NODES];                 // deg -> rsqrt(deg)
__device__ __align__(16) float g_buf1[(size_t)N_NODES * HID];   // h / h2
__device__ __align__(16) float g_buf2[(size_t)N_NODES * HID];   // agg buffers
__device__ __align__(16) float g_sums[N_GRAPHS * HID];
__device__ float g_cnt[N_GRAPHS];
__device__ int   g_is64;

// ---------------------------------------------------------------------------
// Helpers
// ---------------------------------------------------------------------------
__device__ __forceinline__ void red_add_v4(float4* p, float4 v) {
#if defined(__CUDA_ARCH__) && __CUDA_ARCH__ >= 900
    asm volatile("red.global.add.v4.f32 [%0], {%1, %2, %3, %4};"
                 :: "l"(p), "f"(v.x), "f"(v.y), "f"(v.z), "f"(v.w) : "memory");
#else
    float* f = (float*)p;
    atomicAdd(f + 0, v.x); atomicAdd(f + 1, v.y);
    atomicAdd(f + 2, v.z); atomicAdd(f + 3, v.w);
#endif
}

__device__ __forceinline__ int idx_at(const void* p, long long i, int is64) {
    return is64 ? (int)((const long long*)p)[i] : ((const int*)p)[i];
}

// ---------------------------------------------------------------------------
// dtype detection: int64 vs int32 indices (deterministic, data-derived)
// ---------------------------------------------------------------------------
__global__ void k_detect(const void* __restrict__ edges) {
    if (threadIdx.x == 0 && blockIdx.x == 0) {
        const long long* p = (const long long*)edges;
        int is64 = 1;
        for (int i = 0; i < 512; i++) {
            long long v = p[i];
            if (v < 0 || v >= N_NODES) { is64 = 0; break; }
        }
        g_is64 = is64;
    }
}

// ---------------------------------------------------------------------------
// Degree / normalization
// ---------------------------------------------------------------------------
__global__ void k_init_deg() {
    int i = blockIdx.x * blockDim.x + threadIdx.x;
    if (i < N_NODES) g_dinv[i] = 1.0f;  // self-loop
}

__global__ void k_deg_edges(const void* __restrict__ edges) {
    int i = blockIdx.x * blockDim.x + threadIdx.x;
    if (i < N_EDGES) {
        int d = idx_at(edges, (long long)N_EDGES + i, g_is64);
        atomicAdd(&g_dinv[d], 1.0f);
    }
}

__global__ void k_rsqrt() {
    int i = blockIdx.x * blockDim.x + threadIdx.x;
    if (i < N_NODES) g_dinv[i] = rsqrtf(g_dinv[i]);
}

// ---------------------------------------------------------------------------
// Self-loop init: out[i] = H[i] * dinv[i]^2   (also serves as zero-init)
// ---------------------------------------------------------------------------
template <int F>
__global__ void k_self_init(const float* __restrict__ H, float* __restrict__ out) {
    size_t i = (size_t)blockIdx.x * blockDim.x + threadIdx.x;  // over float4s
    size_t total = (size_t)N_NODES * (F / 4);
    if (i >= total) return;
    int node = (int)(i / (F / 4));
    float di = g_dinv[node];
    float s = di * di;
    float4 v = ((const float4*)H)[i];
    v.x *= s; v.y *= s; v.z *= s; v.w *= s;
    ((float4*)out)[i] = v;
}

// ---------------------------------------------------------------------------
// Edge aggregation: out[dst] += H[src] * dinv[src]*dinv[dst]
// One warp per edge; lane strides the feature dim (F/4 float4s).
// ---------------------------------------------------------------------------
template <int F>
__global__ void k_agg(const float* __restrict__ H, float* __restrict__ out,
                      const void* __restrict__ edges) {
    int idx  = blockIdx.x * blockDim.x + threadIdx.x;
    int e    = idx >> 5;
    int lane = idx & 31;
    if (e >= N_EDGES) return;
    int is64 = g_is64;
    int s = idx_at(edges, e, is64);
    int d = idx_at(edges, (long long)N_EDGES + e, is64);
    float norm = g_dinv[s] * g_dinv[d];
    const float4* hs = (const float4*)(H + (size_t)s * F);
    float4* od = (float4*)(out + (size_t)d * F);
#pragma unroll
    for (int it = 0; it < F / 128; it++) {
        int c = lane + it * 32;
        float4 v = hs[c];
        v.x *= norm; v.y *= norm; v.z *= norm; v.w *= norm;
        red_add_v4(od + c, v);
    }
}

// ---------------------------------------------------------------------------
// SIMT SGEMM with fused bias + ReLU:  C[M,N] = relu(A[M,K] @ W[K,N] + b)
// BM=128 BN=64 BK=16, 256 threads, 8x4 per thread.
// ---------------------------------------------------------------------------
template <int BM, int BN, int BK, int TM, int TN>
__global__ void k_gemm_bias_relu(const float* __restrict__ A, const float* __restrict__ W,
                                 const float* __restrict__ bias, float* __restrict__ C,
                                 int M, int N, int K) {
    constexpr int TX = BN / TN;       // 16
    constexpr int TY = BM / TM;       // 16
    constexpr int NT = TX * TY;       // 256
    __shared__ float As[BM][BK];
    __shared__ float Ws[BK][BN];

    const int tid = threadIdx.x;
    const int tx = tid % TX;
    const int ty = tid / TX;
    const int row0 = blockIdx.y * BM;
    const int col0 = blockIdx.x * BN;

    float acc[TM][TN];
#pragma unroll
    for (int i = 0; i < TM; i++)
#pragma unroll
        for (int j = 0; j < TN; j++) acc[i][j] = 0.0f;

    for (int k0 = 0; k0 < K; k0 += BK) {
        // A tile: BM*BK/4 float4 loads
#pragma unroll
        for (int it = 0; it < (BM * BK / 4) / NT; it++) {
            int j = tid + it * NT;
            int m = j / (BK / 4);
            int k4 = j % (BK / 4);
            int gm = row0 + m;
            float4 v = make_float4(0.f, 0.f, 0.f, 0.f);
            if (gm < M) v = *(const float4*)(A + (size_t)gm * K + k0 + k4 * 4);
            *(float4*)(&As[m][k4 * 4]) = v;
        }
        // W tile: BK*BN/4 float4 loads
#pragma unroll
        for (int it = 0; it < (BK * BN / 4) / NT; it++) {
            int j = tid + it * NT;
            int k = j / (BN / 4);
            int n4 = j % (BN / 4);
            *(float4*)(&Ws[k][n4 * 4]) = *(const float4*)(W + (size_t)(k0 + k) * N + col0 + n4 * 4);
        }
        __syncthreads();
#pragma unroll
        for (int k = 0; k < BK; k++) {
            float a[TM], w[TN];
#pragma unroll
            for (int i = 0; i < TM; i++) a[i] = As[ty * TM + i][k];
#pragma unroll
            for (int j = 0; j < TN; j++) w[j] = Ws[k][tx * TN + j];
#pragma unroll
            for (int i = 0; i < TM; i++)
#pragma unroll
                for (int j = 0; j < TN; j++) acc[i][j] += a[i] * w[j];
        }
        __syncthreads();
    }

#pragma unroll
    for (int i = 0; i < TM; i++) {
        int gm = row0 + ty * TM + i;
        if (gm >= M) continue;
#pragma unroll
        for (int j = 0; j < TN; j += 4) {
            int gn = col0 + tx * TN + j;
            float4 v;
            v.x = fmaxf(acc[i][j + 0] + bias[gn + 0], 0.f);
            v.y = fmaxf(acc[i][j + 1] + bias[gn + 1], 0.f);
            v.z = fmaxf(acc[i][j + 2] + bias[gn + 2], 0.f);
            v.w = fmaxf(acc[i][j + 3] + bias[gn + 3], 0.f);
            *(float4*)(C + (size_t)gm * N + gn) = v;
        }
    }
}

// ---------------------------------------------------------------------------
// Pooling: sums[g] += h2[node], cnt[g] += 1
// ---------------------------------------------------------------------------
__global__ void k_zero_pool() {
    int i = blockIdx.x * blockDim.x + threadIdx.x;
    if (i < N_GRAPHS * HID) g_sums[i] = 0.0f;
    if (i < N_GRAPHS) g_cnt[i] = 0.0f;
}

__global__ void k_pool(const float* __restrict__ H, const void* __restrict__ batch) {
    size_t i = (size_t)blockIdx.x * blockDim.x + threadIdx.x;  // node*64 + f4
    if (i >= (size_t)N_NODES * (HID / 4)) return;
    int node = (int)(i >> 6);
    int f4 = (int)(i & 63);
    int g = idx_at(batch, node, g_is64);
    float4 v = ((const float4*)H)[(size_t)node * (HID / 4) + f4];
    red_add_v4((float4*)g_sums + g * (HID / 4) + f4, v);
    if (f4 == 0) atomicAdd(&g_cnt[g], 1.0f);
}

// ---------------------------------------------------------------------------
// Final: pooled @ fc_w + fc_b, log_softmax over 2 classes
// ---------------------------------------------------------------------------
__global__ void k_final(const float* __restrict__ fcw, const float* __restrict__ fcb,
                        float* __restrict__ out) {
    int g = threadIdx.x;
    if (g >= N_GRAPHS) return;
    float inv = 1.0f / fmaxf(g_cnt[g], 1.0f);
    float l0 = fcb[0], l1 = fcb[1];
#pragma unroll 8
    for (int f = 0; f < HID; f++) {
        float p = g_sums[g * HID + f] * inv;
        l0 += p * fcw[f * N_CLS + 0];
        l1 += p * fcw[f * N_CLS + 1];
    }
    float m = fmaxf(l0, l1);
    float lse = m + logf(expf(l0 - m) + expf(l1 - m));
    out[g * N_CLS + 0] = l0 - lse;
    out[g * N_CLS + 1] = l1 - lse;
}

// ---------------------------------------------------------------------------
// Launch
// ---------------------------------------------------------------------------
extern "C" void kernel_launch(void* const* d_in, const int* in_sizes, int n_in,
                              void* d_out, int out_size) {
    const float* x     = (const float*)d_in[0];
    const void*  edges = d_in[1];
    const void*  batch = d_in[2];
    const float* W1    = (const float*)d_in[3];
    const float* b1    = (const float*)d_in[4];
    const float* W2    = (const float*)d_in[5];
    const float* b2    = (const float*)d_in[6];
    const float* fcw   = (const float*)d_in[7];
    const float* fcb   = (const float*)d_in[8];
    float* out = (float*)d_out;

    const int T = 256;
    k_detect<<<1, 32>>>(edges);

    // deg -> dinv
    k_init_deg<<<(N_NODES + T - 1) / T, T>>>();
    k_deg_edges<<<(N_EDGES + T - 1) / T, T>>>(edges);
    k_rsqrt<<<(N_NODES + T - 1) / T, T>>>();

    // Layer 1: aggregate-first (F=128), then GEMM(128->256)+bias+relu
    {
        int nf4 = N_NODES * (F_IN / 4);
        k_self_init<F_IN><<<(nf4 + T - 1) / T, T>>>(x, g_buf2);
        long long nthr = (long long)N_EDGES * 32;
        k_agg<F_IN><<<(unsigned)((nthr + T - 1) / T), T>>>(x, g_buf2, edges);
        dim3 grid(HID / 64, (N_NODES + 127) / 128);
        k_gemm_bias_relu<128, 64, 16, 8, 4><<<grid, 256>>>(g_buf2, W1, b1, g_buf1,
                                                           N_NODES, HID, F_IN);
    }

    // Layer 2: aggregate (F=256), then GEMM(256->256)+bias+relu
    {
        int nf4 = N_NODES * (HID / 4);
        k_self_init<HID><<<(nf4 + T - 1) / T, T>>>(g_buf1, g_buf2);
        long long nthr = (long long)N_EDGES * 32;
        k_agg<HID><<<(unsigned)((nthr + T - 1) / T), T>>>(g_buf1, g_buf2, edges);
        dim3 grid(HID / 64, (N_NODES + 127) / 128);
        k_gemm_bias_relu<128, 64, 16, 8, 4><<<grid, 256>>>(g_buf2, W2, b2, g_buf1,
                                                           N_NODES, HID, HID);
    }

    // Pool + FC + log_softmax
    k_zero_pool<<<(N_GRAPHS * HID + T - 1) / T, T>>>();
    {
        long long nthr = (long long)N_NODES * (HID / 4);
        k_pool<<<(unsigned)((nthr + T - 1) / T), T>>>(g_buf1, batch);
    }
    k_final<<<1, 64>>>(fcw, fcb, out);
}

// round 2
// speedup vs baseline: 2.6836x; 2.6836x over previous
#include <cuda_runtime.h>
#include <math.h>

// Problem constants
#define N_NODES  100000
#define N_EDGES  3200000
#define N_GRAPHS 64
#define F_IN     128
#define HID      256
#define N_CLS    2

// ---------------------------------------------------------------------------
// Scratch (__device__ globals — allocation-free)
// ---------------------------------------------------------------------------
__device__ __align__(16) float g_dinv[N_NODES];
__device__ __align__(16) int   g_deg[N_NODES];
__device__ __align__(16) int   g_rowptr[N_NODES + 1];
__device__ __align__(16) int   g_cursor[N_NODES];
__device__ __align__(16) int   g_csr_src[N_EDGES];
__device__ __align__(16) float g_csr_nrm[N_EDGES];
__device__ __align__(16) float g_buf1[(size_t)N_NODES * HID];
__device__ __align__(16) float g_buf2[(size_t)N_NODES * HID];
__device__ __align__(16) float g_sums[N_GRAPHS * HID];
__device__ float g_cnt[N_GRAPHS];
__device__ int   g_is64;

// ---------------------------------------------------------------------------
__device__ __forceinline__ void red_add_v4(float4* p, float4 v) {
    asm volatile("red.global.add.v4.f32 [%0], {%1, %2, %3, %4};"
                 :: "l"(p), "f"(v.x), "f"(v.y), "f"(v.z), "f"(v.w) : "memory");
}

__device__ __forceinline__ int idx_at(const void* p, long long i, int is64) {
    return is64 ? (int)((const long long*)p)[i] : ((const int*)p)[i];
}

// ---------------------------------------------------------------------------
// 1) detect index dtype + zero degree counters
// ---------------------------------------------------------------------------
__global__ void k_prep(const void* __restrict__ edges) {
    int i = blockIdx.x * blockDim.x + threadIdx.x;
    if (i < N_NODES) g_deg[i] = 0;
    if (i == 0) {
        const long long* p = (const long long*)edges;
        int is64 = 1;
        for (int j = 0; j < 512; j++) {
            long long v = p[j];
            if (v < 0 || v >= N_NODES) { is64 = 0; break; }
        }
        g_is64 = is64;
    }
}

// 2) degree count (in-degree, excluding self-loop)
__global__ void k_deg(const void* __restrict__ edges) {
    int i = blockIdx.x * blockDim.x + threadIdx.x;
    if (i < N_EDGES) {
        int d = idx_at(edges, (long long)N_EDGES + i, g_is64);
        atomicAdd(&g_deg[d], 1);
    }
}

// 3) single-block exclusive scan (rowptr, cursor) + dinv = rsqrt(deg+1)
__global__ void k_scan_rsqrt() {
    const int T = 1024;
    const int CH = (N_NODES + T - 1) / T;  // 98
    __shared__ int part[T];
    int t = threadIdx.x;
    int base = t * CH;
    int local = 0;
    for (int i = 0; i < CH; i++) {
        int idx = base + i;
        if (idx < N_NODES) local += g_deg[idx];
    }
    part[t] = local;
    __syncthreads();
    // inclusive Hillis-Steele
    for (int off = 1; off < T; off <<= 1) {
        int v = (t >= off) ? part[t - off] : 0;
        __syncthreads();
        if (t >= off) part[t] += v;
        __syncthreads();
    }
    int prefix = (t == 0) ? 0 : part[t - 1];
    for (int i = 0; i < CH; i++) {
        int idx = base + i;
        if (idx < N_NODES) {
            g_rowptr[idx] = prefix;
            g_cursor[idx] = prefix;
            prefix += g_deg[idx];
        }
    }
    if (t == T - 1) g_rowptr[N_NODES] = part[T - 1];
    __syncthreads();
    for (int i = t; i < N_NODES; i += T)
        g_dinv[i] = rsqrtf((float)(g_deg[i] + 1));
}

// 4) CSR fill: slot = cursor[dst]++; store src and precomputed norm
__global__ void k_fill(const void* __restrict__ edges) {
    int e = blockIdx.x * blockDim.x + threadIdx.x;
    if (e >= N_EDGES) return;
    int is64 = g_is64;
    int s = idx_at(edges, e, is64);
    int d = idx_at(edges, (long long)N_EDGES + e, is64);
    int slot = atomicAdd(&g_cursor[d], 1);
    g_csr_src[slot] = s;
    g_csr_nrm[slot] = g_dinv[s] * g_dinv[d];
}

// ---------------------------------------------------------------------------
// Pull-style aggregation: one block (128 threads) per dst node.
// out[d] = dinv[d]^2 * H[d] + sum_e nrm[e] * H[src[e]]
// ---------------------------------------------------------------------------
template <int F>
__global__ void __launch_bounds__(128) k_agg_csr(const float* __restrict__ H,
                                                 float* __restrict__ out) {
    constexpr int C = F / 128;          // cols per thread
    constexpr int CHUNK = 128;
    __shared__ int   s_src[CHUNK];
    __shared__ float s_nrm[CHUNK];

    int node = blockIdx.x;
    int tid = threadIdx.x;
    int beg = g_rowptr[node];
    int end = g_rowptr[node + 1];

    float di = g_dinv[node];
    float self = di * di;
    float acc[C];
#pragma unroll
    for (int c = 0; c < C; c++)
        acc[c] = self * __ldg(H + (size_t)node * F + tid + c * 128);

    for (int p = beg; p < end; p += CHUNK) {
        int n = min(CHUNK, end - p);
        if (tid < n) {
            s_src[tid] = g_csr_src[p + tid];
            s_nrm[tid] = g_csr_nrm[p + tid];
        }
        __syncthreads();
        int j = 0;
        // unroll-by-4 to expose load-level parallelism
        for (; j + 4 <= n; j += 4) {
            int   s0 = s_src[j],     s1 = s_src[j + 1],
                  s2 = s_src[j + 2], s3 = s_src[j + 3];
            float w0 = s_nrm[j],     w1 = s_nrm[j + 1],
                  w2 = s_nrm[j + 2], w3 = s_nrm[j + 3];
#pragma unroll
            for (int c = 0; c < C; c++) {
                float v0 = __ldg(H + (size_t)s0 * F + tid + c * 128);
                float v1 = __ldg(H + (size_t)s1 * F + tid + c * 128);
                float v2 = __ldg(H + (size_t)s2 * F + tid + c * 128);
                float v3 = __ldg(H + (size_t)s3 * F + tid + c * 128);
                acc[c] += v0 * w0;
                acc[c] += v1 * w1;
                acc[c] += v2 * w2;
                acc[c] += v3 * w3;
            }
        }
        for (; j < n; j++) {
            int s = s_src[j];
            float w = s_nrm[j];
#pragma unroll
            for (int c = 0; c < C; c++)
                acc[c] += __ldg(H + (size_t)s * F + tid + c * 128) * w;
        }
        __syncthreads();
    }
#pragma unroll
    for (int c = 0; c < C; c++)
        out[(size_t)node * F + tid + c * 128] = acc[c];
}

// ---------------------------------------------------------------------------
// SGEMM + bias + ReLU. BM=128, BN=64, BK=16, 128 threads, 8x8/thread.
// A-tile stored transposed in smem (conflict-free reads).
// ---------------------------------------------------------------------------
template <int BM, int BN, int BK, int TM, int TN>
__global__ void __launch_bounds__(128) k_gemm_bias_relu(
    const float* __restrict__ A, const float* __restrict__ W,
    const float* __restrict__ bias, float* __restrict__ C_,
    int M, int N, int K) {
    constexpr int TX = BN / TN;   // 8
    constexpr int TY = BM / TM;   // 16
    constexpr int NT = TX * TY;   // 128
    __shared__ float Ast[BK][BM];
    __shared__ float Ws[BK][BN];

    const int tid = threadIdx.x;
    const int tx = tid % TX;
    const int ty = tid / TX;
    const int row0 = blockIdx.y * BM;
    const int col0 = blockIdx.x * BN;

    float acc[TM][TN];
#pragma unroll
    for (int i = 0; i < TM; i++)
#pragma unroll
        for (int j = 0; j < TN; j++) acc[i][j] = 0.0f;

    for (int k0 = 0; k0 < K; k0 += BK) {
        // A tile (transposed store): BM*BK/4 float4 loads
#pragma unroll
        for (int it = 0; it < (BM * BK / 4) / NT; it++) {
            int j = tid + it * NT;
            int m = j / (BK / 4);
            int k4 = j % (BK / 4);
            int gm = row0 + m;
            float4 v = make_float4(0.f, 0.f, 0.f, 0.f);
            if (gm < M) v = *(const float4*)(A + (size_t)gm * K + k0 + k4 * 4);
            Ast[k4 * 4 + 0][m] = v.x;
            Ast[k4 * 4 + 1][m] = v.y;
            Ast[k4 * 4 + 2][m] = v.z;
            Ast[k4 * 4 + 3][m] = v.w;
        }
        // W tile
#pragma unroll
        for (int it = 0; it < (BK * BN / 4) / NT; it++) {
            int j = tid + it * NT;
            int k = j / (BN / 4);
            int n4 = j % (BN / 4);
            *(float4*)(&Ws[k][n4 * 4]) =
                *(const float4*)(W + (size_t)(k0 + k) * N + col0 + n4 * 4);
        }
        __syncthreads();
#pragma unroll
        for (int k = 0; k < BK; k++) {
            float a[TM], w[TN];
            *(float4*)(a)     = *(float4*)(&Ast[k][ty * TM]);
            *(float4*)(a + 4) = *(float4*)(&Ast[k][ty * TM + 4]);
            *(float4*)(w)     = *(float4*)(&Ws[k][tx * TN]);
            *(float4*)(w + 4) = *(float4*)(&Ws[k][tx * TN + 4]);
#pragma unroll
            for (int i = 0; i < TM; i++)
#pragma unroll
                for (int j = 0; j < TN; j++) acc[i][j] += a[i] * w[j];
        }
        __syncthreads();
    }

#pragma unroll
    for (int i = 0; i < TM; i++) {
        int gm = row0 + ty * TM + i;
        if (gm >= M) continue;
#pragma unroll
        for (int j = 0; j < TN; j += 4) {
            int gn = col0 + tx * TN + j;
            float4 v;
            v.x = fmaxf(acc[i][j + 0] + bias[gn + 0], 0.f);
            v.y = fmaxf(acc[i][j + 1] + bias[gn + 1], 0.f);
            v.z = fmaxf(acc[i][j + 2] + bias[gn + 2], 0.f);
            v.w = fmaxf(acc[i][j + 3] + bias[gn + 3], 0.f);
            *(float4*)(C_ + (size_t)gm * N + gn) = v;
        }
    }
}

// ---------------------------------------------------------------------------
// Pool + final
// ---------------------------------------------------------------------------
__global__ void k_zero_pool() {
    int i = blockIdx.x * blockDim.x + threadIdx.x;
    if (i < N_GRAPHS * HID) g_sums[i] = 0.0f;
    if (i < N_GRAPHS) g_cnt[i] = 0.0f;
}

__global__ void k_pool(const float* __restrict__ H, const void* __restrict__ batch) {
    size_t i = (size_t)blockIdx.x * blockDim.x + threadIdx.x;
    if (i >= (size_t)N_NODES * (HID / 4)) return;
    int node = (int)(i >> 6);
    int f4 = (int)(i & 63);
    int g = idx_at(batch, node, g_is64);
    float4 v = ((const float4*)H)[(size_t)node * (HID / 4) + f4];
    red_add_v4((float4*)g_sums + g * (HID / 4) + f4, v);
    if (f4 == 0) atomicAdd(&g_cnt[g], 1.0f);
}

__global__ void k_final(const float* __restrict__ fcw, const float* __restrict__ fcb,
                        float* __restrict__ out) {
    int g = threadIdx.x;
    if (g >= N_GRAPHS) return;
    float inv = 1.0f / fmaxf(g_cnt[g], 1.0f);
    float l0 = fcb[0], l1 = fcb[1];
#pragma unroll 8
    for (int f = 0; f < HID; f++) {
        float p = g_sums[g * HID + f] * inv;
        l0 += p * fcw[f * N_CLS + 0];
        l1 += p * fcw[f * N_CLS + 1];
    }
    float m = fmaxf(l0, l1);
    float lse = m + logf(expf(l0 - m) + expf(l1 - m));
    out[g * N_CLS + 0] = l0 - lse;
    out[g * N_CLS + 1] = l1 - lse;
}

// ---------------------------------------------------------------------------
extern "C" void kernel_launch(void* const* d_in, const int* in_sizes, int n_in,
                              void* d_out, int out_size) {
    const float* x     = (const float*)d_in[0];
    const void*  edges = d_in[1];
    const void*  batch = d_in[2];
    const float* W1    = (const float*)d_in[3];
    const float* b1    = (const float*)d_in[4];
    const float* W2    = (const float*)d_in[5];
    const float* b2    = (const float*)d_in[6];
    const float* fcw   = (const float*)d_in[7];
    const float* fcb   = (const float*)d_in[8];
    float* out = (float*)d_out;

    const int T = 256;

    // CSR build
    k_prep<<<(N_NODES + T - 1) / T, T>>>(edges);
    k_deg<<<(N_EDGES + T - 1) / T, T>>>(edges);
    k_scan_rsqrt<<<1, 1024>>>();
    k_fill<<<(N_EDGES + T - 1) / T, T>>>(edges);

    // Layer 1: aggregate (F=128) pull-style, then GEMM(128->256)+bias+relu
    k_agg_csr<F_IN><<<N_NODES, 128>>>(x, g_buf2);
    {
        dim3 grid(HID / 64, (N_NODES + 127) / 128);
        k_gemm_bias_relu<128, 64, 16, 8, 8><<<grid, 128>>>(g_buf2, W1, b1, g_buf1,
                                                           N_NODES, HID, F_IN);
    }

    // Layer 2: aggregate (F=256), then GEMM(256->256)+bias+relu
    k_agg_csr<HID><<<N_NODES, 128>>>(g_buf1, g_buf2);
    {
        dim3 grid(HID / 64, (N_NODES + 127) / 128);
        k_gemm_bias_relu<128, 64, 16, 8, 8><<<grid, 128>>>(g_buf2, W2, b2, g_buf1,
                                                           N_NODES, HID, HID);
    }

    // Pool + FC + log_softmax
    k_zero_pool<<<(N_GRAPHS * HID + T - 1) / T, T>>>();
    {
        long long nthr = (long long)N_NODES * (HID / 4);
        k_pool<<<(unsigned)((nthr + T - 1) / T), T>>>(g_buf1, batch);
    }
    k_final<<<1, 64>>>(fcw, fcb, out);
}